// round 16
// baseline (speedup 1.0000x reference)
#include <cuda_runtime.h>
#include <cuda_fp16.h>
#include <stdint.h>

#define NN 4096
#define DD 70
#define SSTR 72                   // padded row length (floats) in partial buffer
#define KC 64                     // K per chunk
#define KQUART 1024
#define NCH 16                    // chunks per CTA (K-quarter)
#define MTILE 256
#define TPB 256

// B chunk image: fragment-packed fp16 (hi only). For (kt 0..3, nt 0..8, lane 0..31):
//   uint2 {bh0, bh1} at offset ((kt*9+nt)*32 + lane)*8
#define B_IMG 9216                // 4*9*32*8
#define B_VEC16 (B_IMG / 16)      // 576
#define SMEM_TOTAL (3 * B_IMG)    // 27648 (triple-buffered B stages)

// ---- device scratch (no allocs allowed) ----
__device__ __align__(16) unsigned char g_sb[64 * B_IMG];     // 590 KB, L2-resident
__device__ float g_part[(size_t)2 * 4 * NN * SSTR];          // 9.4 MB partials (2 dir x 4 kq)

__device__ __forceinline__ uint32_t smem_u32(const void* p) {
    uint32_t a;
    asm("{ .reg .u64 t; cvta.to.shared.u64 t, %1; cvt.u32.u64 %0, t; }" : "=r"(a) : "l"(p));
    return a;
}

// split a pair of fp32 into packed fp16x2 hi and lo (residual)
__device__ __forceinline__ void splitA(float x, float y, uint32_t& h, uint32_t& l) {
    __half2 hh = __floats2half2_rn(x, y);
    float2 hf = __half22float2(hh);
    __half2 ll = __floats2half2_rn(x - hf.x, y - hf.y);
    h = *reinterpret_cast<uint32_t*>(&hh);
    l = *reinterpret_cast<uint32_t*>(&ll);
}
__device__ __forceinline__ uint32_t packH(float x, float y) {
    __half2 hh = __floats2half2_rn(x, y);
    return *reinterpret_cast<uint32_t*>(&hh);
}

__device__ __forceinline__ void mma_f16(float* d, const uint32_t* a, uint32_t b0, uint32_t b1) {
    asm volatile(
        "mma.sync.aligned.m16n8k16.row.col.f32.f16.f16.f32 "
        "{%0,%1,%2,%3}, {%4,%5,%6,%7}, {%8,%9}, {%0,%1,%2,%3};"
        : "+f"(d[0]), "+f"(d[1]), "+f"(d[2]), "+f"(d[3])
        : "r"(a[0]), "r"(a[1]), "r"(a[2]), "r"(a[3]), "r"(b0), "r"(b1));
}

// ---------------- kernel 1: build fragment-packed B images (fp16 hi only) ----------------
__global__ void prep_s_kernel(const float* __restrict__ s) {
    int lane = threadIdx.x;            // 0..31
    int nt   = threadIdx.y;            // 0..8
    int kt   = blockIdx.x;             // 0..3
    int c    = blockIdx.y;             // 0..63
    int r4 = lane >> 2, q4 = lane & 3;
    int d  = nt * 8 + r4;
    int k0 = c * KC + kt * 16 + q4 * 2;
    float s0 = 0.f, s1 = 0.f, s8 = 0.f, s9 = 0.f;
    if (d < DD) {
        s0 = s[(size_t)k0 * DD + d];
        s1 = s[(size_t)(k0 + 1) * DD + d];
        s8 = s[(size_t)(k0 + 8) * DD + d];
        s9 = s[(size_t)(k0 + 9) * DD + d];
    }
    uint2 v = make_uint2(packH(s0, s1), packH(s8, s9));
    *(uint2*)(g_sb + (size_t)c * B_IMG + ((kt * 9 + nt) * 32 + lane) * 8) = v;
}

// ---------------- kernel 2: split-fp16 mma.sync GEMM, M=256/CTA, K-split 4 ----------------
// block b: dir = b>>6, kq = (b>>4)&3, mt = b&15.  Warp covers 32 rows (2 m-fragments).
__global__ __launch_bounds__(TPB, 1)
void slayer_mma_kernel(const float* __restrict__ adj)
{
    extern __shared__ unsigned char smem[];
    const uint32_t sb = smem_u32(smem);
    const int tid  = threadIdx.x;
    const int wid  = tid >> 5;
    const int lane = tid & 31;
    const int b    = blockIdx.x;
    const int dir  = b >> 6;
    const int kq   = (b >> 4) & 3;
    const int mt   = b & 15;
    const int rowbase = mt * MTILE;
    const int kbase   = kq * KQUART;
    const int cbase   = kq * NCH;
    const bool trans  = (dir == 1);

    const int r4 = lane >> 2;   // 0..7
    const int q4 = lane & 3;    // 0..3
    const int w32 = rowbase + wid * 32;
    const int rA = w32 + r4;          // frag 0 base row
    const int rB = w32 + 16 + r4;     // frag 1 base row

    float acc[2][9][4];
#pragma unroll
    for (int f = 0; f < 2; f++)
#pragma unroll
        for (int nt = 0; nt < 9; nt++)
#pragma unroll
            for (int u = 0; u < 4; u++) acc[f][nt][u] = 0.0f;

    float praw[64];              // channel-summed A prefetch: [f*32 + kt*8 + u]
    uint32_t afh[32], afl[32];   // A fragments current chunk: [f*16 + kt*4 + u]

    // semantic order per (f, kt): u0=(r,k0) u1=(r,k0+1) u2=(r+8,k0) u3=(r+8,k0+1)
    //                             u4=(r,k0+8) u5=(r,k0+9) u6=(r+8,k0+8) u7=(r+8,k0+9)
#define PREF_A(ci)                                                              \
    do {                                                                        \
        const int kc_ = kbase + (ci) * KC;                                      \
        _Pragma("unroll")                                                       \
        for (int f = 0; f < 2; f++) {                                           \
            const int rr = (f == 0) ? rA : rB;                                  \
            if (!trans) {                                                       \
                _Pragma("unroll")                                               \
                for (int kt = 0; kt < 4; kt++) {                                \
                    const int k0_ = kc_ + kt * 16 + q4 * 2;                     \
                    const float4* p0 = (const float4*)(adj + (((size_t)rr) * NN + k0_) * 2);      \
                    const float4* p1 = (const float4*)(adj + (((size_t)(rr + 8)) * NN + k0_) * 2);\
                    float4 g;                                                   \
                    float* ps = praw + f * 32 + kt * 8;                         \
                    g = p0[0]; ps[0] = g.x + g.y; ps[1] = g.z + g.w;            \
                    g = p1[0]; ps[2] = g.x + g.y; ps[3] = g.z + g.w;            \
                    g = p0[4]; ps[4] = g.x + g.y; ps[5] = g.z + g.w;            \
                    g = p1[4]; ps[6] = g.x + g.y; ps[7] = g.z + g.w;            \
                }                                                               \
            } else {                                                            \
                _Pragma("unroll")                                               \
                for (int kt = 0; kt < 4; kt++) {                                \
                    const int k0_ = kc_ + kt * 16 + q4 * 2;                     \
                    float* ps = praw + f * 32 + kt * 8;                         \
                    float2 g;                                                   \
                    _Pragma("unroll")                                           \
                    for (int u = 0; u < 8; u++) {                               \
                        const int ki = k0_ + (u >> 2) * 8 + (u & 1);            \
                        const int ji = rr + ((u >> 1) & 1) * 8;                 \
                        g = *(const float2*)(adj + (((size_t)ki) * NN + ji) * 2);\
                        ps[u] = g.x + g.y;                                      \
                    }                                                           \
                }                                                               \
            }                                                                   \
        }                                                                       \
    } while (0)

#define CONV_A()                                                                \
    do {                                                                        \
        _Pragma("unroll")                                                       \
        for (int f = 0; f < 2; f++)                                             \
            _Pragma("unroll")                                                   \
            for (int kt = 0; kt < 4; kt++) {                                    \
                const float* ps = praw + f * 32 + kt * 8;                       \
                uint32_t* h = afh + f * 16 + kt * 4;                            \
                uint32_t* l = afl + f * 16 + kt * 4;                            \
                splitA(ps[0], ps[1], h[0], l[0]);                               \
                splitA(ps[2], ps[3], h[1], l[1]);                               \
                splitA(ps[4], ps[5], h[2], l[2]);                               \
                splitA(ps[6], ps[7], h[3], l[3]);                               \
            }                                                                   \
    } while (0)

    // cp.async B stage fill: 576 uint4, 256 threads -> 2 full + 1 guarded
#define ISSUE_B(ci)                                                             \
    do {                                                                        \
        const unsigned char* src_ = g_sb + (size_t)(cbase + (ci)) * B_IMG;      \
        uint32_t dst_ = sb + (uint32_t)(((ci) % 3) * B_IMG);                    \
        _Pragma("unroll")                                                       \
        for (int u = 0; u < 2; u++) {                                           \
            int t_ = tid + u * TPB;                                             \
            asm volatile("cp.async.cg.shared.global [%0], [%1], 16;"            \
                         :: "r"(dst_ + t_ * 16), "l"(src_ + (size_t)t_ * 16));  \
        }                                                                       \
        if (tid < B_VEC16 - 2 * TPB) {                                          \
            int t_ = tid + 2 * TPB;                                             \
            asm volatile("cp.async.cg.shared.global [%0], [%1], 16;"            \
                         :: "r"(dst_ + t_ * 16), "l"(src_ + (size_t)t_ * 16));  \
        }                                                                       \
    } while (0)
#define CP_COMMIT() asm volatile("cp.async.commit_group;" ::: "memory")
#define CP_WAIT1()  asm volatile("cp.async.wait_group 1;" ::: "memory")

    // ---- prologue ----
    ISSUE_B(0); CP_COMMIT();
    ISSUE_B(1); CP_COMMIT();
    PREF_A(0);
    CONV_A();            // chunk 0 fragments ready
    PREF_A(1);           // in flight; consumed after chunk 0's MMAs

    for (int ci = 0; ci < NCH; ci++) {
        CP_WAIT1();           // B group(ci) complete
        __syncthreads();      // publish stage ci%3; all warps done reading stage (ci+2)%3
        if (ci + 2 < NCH) ISSUE_B(ci + 2);
        CP_COMMIT();          // uniform group count (empty on tail)

        const unsigned char* bstage = smem + (ci % 3) * B_IMG + lane * 8;

        // ---- MMA: 4 kt x 9 nt x (2 frags x 2 products), B loaded once per (kt,nt) ----
#pragma unroll
        for (int kt = 0; kt < 4; kt++) {
            const uint32_t* h0 = afh + kt * 4;
            const uint32_t* l0 = afl + kt * 4;
            const uint32_t* h1 = afh + 16 + kt * 4;
            const uint32_t* l1 = afl + 16 + kt * 4;
#pragma unroll
            for (int nt = 0; nt < 9; nt++) {
                uint2 bf = *(const uint2*)(bstage + (kt * 9 + nt) * 256);
                mma_f16(acc[0][nt], h0, bf.x, bf.y);
                mma_f16(acc[0][nt], l0, bf.x, bf.y);
                mma_f16(acc[1][nt], h1, bf.x, bf.y);
                mma_f16(acc[1][nt], l1, bf.x, bf.y);
            }
        }

        // ---- pipeline turn: convert prefetched chunk ci+1, prefetch ci+2 ----
        if (ci + 1 < NCH) {
            CONV_A();
            if (ci + 2 < NCH) PREF_A(ci + 2);
        }
    }

    // ---- epilogue: write partials (segment = dir*4 + kq) ----
#pragma unroll
    for (int f = 0; f < 2; f++) {
        const int rr = (f == 0) ? rA : rB;
        float* pb = g_part + (((size_t)(dir * 4 + kq) * NN) + rr) * SSTR + q4 * 2;
#pragma unroll
        for (int nt = 0; nt < 9; nt++) {
            *(float2*)(pb + nt * 8)            = make_float2(acc[f][nt][0], acc[f][nt][1]);
            *(float2*)(pb + 8 * SSTR + nt * 8) = make_float2(acc[f][nt][2], acc[f][nt][3]);
        }
    }
#undef PREF_A
#undef CONV_A
#undef ISSUE_B
#undef CP_COMMIT
#undef CP_WAIT1
}

// ---------------- kernel 3: sum 4 K-quarters, write (s_in, s_out) ----------------
__global__ void reduce_kernel(float* __restrict__ out) {
    int e = blockIdx.x * blockDim.x + threadIdx.x;
    if (e >= 2 * NN * DD) return;
    int dirr = e / (NN * DD);
    int rem  = e - dirr * NN * DD;
    int row  = rem / DD;
    int dcol = rem - row * DD;
    const float* p = g_part + ((size_t)(dirr * 4) * NN + row) * SSTR + dcol;
    float v = p[0] + p[(size_t)NN * SSTR] + p[(size_t)2 * NN * SSTR] + p[(size_t)3 * NN * SSTR];
    size_t ob = (dirr == 1) ? 0 : (size_t)NN * DD;   // dir 1 (trans) = s_in first
    out[ob + (size_t)row * DD + dcol] = v;
}

extern "C" void kernel_launch(void* const* d_in, const int* in_sizes, int n_in,
                              void* d_out, int out_size)
{
    const float* adj = (const float*)d_in[0];
    const float* s   = (const float*)d_in[1];
    float* out       = (float*)d_out;

    static bool attr_done = false;
    if (!attr_done) {
        cudaFuncSetAttribute(slayer_mma_kernel,
                             cudaFuncAttributeMaxDynamicSharedMemorySize, SMEM_TOTAL);
        attr_done = true;
    }

    prep_s_kernel<<<dim3(4, 64), dim3(32, 9)>>>(s);
    slayer_mma_kernel<<<128, TPB, SMEM_TOTAL>>>(adj);
    reduce_kernel<<<(2 * NN * DD + TPB - 1) / TPB, TPB>>>(out);
}